// round 9
// baseline (speedup 1.0000x reference)
#include <cuda_runtime.h>

#define MAXN 400000
#define MAXF 2000000
#define MAXE (4 * MAXF)             // max crossing edges (<=4 per valid tet)
#define MAXSLOTNS (6 * MAXF)        // slot namespace (6f+e) for idxmap
#define MAXVAL (MAXN + MAXE)
#define MAXT (3 * MAXF)
#define TPB 256
#define STPB 128                    // sort block (4 warps)
#define SPAN 1024                   // max keys per warp span (8KB smem/warp)
#define GRID(n) (((n) + TPB - 1) / TPB)
#define FULL 0xffffffffu

// key layout: [0:24) slot | [24:44) b | [44:53) aux = (localRank<<1)|head
#define KEY_SLOT(k)  ((unsigned)((k) & 0xFFFFFFull))
#define KEY_B(k)     ((unsigned)(((k) >> 24) & 0xFFFFFull))
#define KEY_AUX(k)   ((unsigned)((k) >> 44))

// ---------------------------------------------------------------------------
// Tables
// ---------------------------------------------------------------------------
__device__ const int d_tri[16][6] = {
    {-1,-1,-1,-1,-1,-1},{1,0,2,-1,-1,-1},{4,0,3,-1,-1,-1},{1,4,2,1,3,4},
    {3,1,5,-1,-1,-1},{2,3,0,2,5,3},{1,4,0,1,5,4},{4,2,5,-1,-1,-1},
    {4,5,2,-1,-1,-1},{4,1,0,4,5,1},{3,2,0,3,5,2},{1,3,5,-1,-1,-1},
    {4,1,2,4,3,1},{3,0,4,-1,-1,-1},{2,0,1,-1,-1,-1},{-1,-1,-1,-1,-1,-1}};
__device__ const int d_tet[16][12] = {
    {-1,-1,-1,-1,-1,-1,-1,-1,-1,-1,-1,-1},{0,4,5,6,-1,-1,-1,-1,-1,-1,-1,-1},
    {1,4,8,7,-1,-1,-1,-1,-1,-1,-1,-1},{7,1,8,6,5,1,7,6,5,0,1,6},
    {2,5,7,9,-1,-1,-1,-1,-1,-1,-1,-1},{4,0,6,7,9,0,7,6,7,0,9,2},
    {4,1,9,8,5,1,9,4,5,1,2,9},{6,0,1,2,8,6,1,2,9,6,8,2},
    {3,6,9,8,-1,-1,-1,-1,-1,-1,-1,-1},{5,0,4,8,5,0,8,3,5,8,9,3},
    {1,4,7,3,4,7,6,3,9,6,7,3},{0,1,5,3,5,1,9,3,5,1,7,9},
    {5,2,3,7,3,6,5,8,3,5,7,8},{0,4,7,8,0,3,8,7,0,3,7,2},
    {4,1,2,3,4,3,2,5,4,3,5,6},{0,1,2,3,-1,-1,-1,-1,-1,-1,-1,-1}};
__device__ const int d_be[12] = {0,1, 0,2, 0,3, 1,2, 1,3, 2,3};

__device__ __forceinline__ unsigned f_valid(unsigned ti) { return (0x7FFEu >> ti) & 1u; }
__device__ __forceinline__ unsigned f_nt1(unsigned ti)   { return (0x6996u >> ti) & 1u; }
__device__ __forceinline__ unsigned f_ntt1(unsigned ti)  { return (0x0116u >> ti) & 1u; }

__device__ __forceinline__ unsigned long long packflags(unsigned ti) {
    unsigned v  = f_valid(ti);
    unsigned n1 = v & f_nt1(ti);
    unsigned t1 = v & f_ntt1(ti);
    unsigned n2 = v ^ n1;
    unsigned t3 = v ^ t1;
    unsigned in = (ti == 15u) ? 1u : 0u;
    return (unsigned long long)n1
         | ((unsigned long long)n2 << 12)
         | ((unsigned long long)t1 << 24)
         | ((unsigned long long)t3 << 36)
         | ((unsigned long long)in << 48);
}

__device__ __forceinline__ unsigned warp_iscan_u32(unsigned x, int lane) {
#pragma unroll
    for (int d = 1; d < 32; d <<= 1) {
        unsigned y = __shfl_up_sync(FULL, x, d);
        if (lane >= d) x += y;
    }
    return x;
}

__device__ __forceinline__ unsigned long long warp_iscan_u64(unsigned long long x, int lane) {
#pragma unroll
    for (int d = 1; d < 32; d <<= 1) {
        unsigned long long y = __shfl_up_sync(FULL, x, d);
        if (lane >= d) x += y;
    }
    return x;
}

// ---------------------------------------------------------------------------
// Scratch
// ---------------------------------------------------------------------------
__device__ unsigned           g_obits[(MAXN + 31) / 32];
__device__ unsigned char      g_ti[MAXF];
__device__ unsigned           g_bcnt[MAXN];
__device__ unsigned           g_boff[MAXN];
__device__ unsigned           g_bfill[MAXN];
__device__ unsigned           g_ucnt[MAXN];
__device__ unsigned           g_urank[MAXN];
__device__ unsigned long long g_keys[MAXE];
__device__ int                g_idxmap[MAXSLOTNS];
__device__ int4               g_alltets[MAXT];
__device__ uint4              g_pres4[(MAXVAL + 15) / 16];
__device__ unsigned           g_rank2[MAXVAL];
__device__ unsigned           g_partf[5 * 1024];
__device__ unsigned           g_part2[4096];
__device__ unsigned long long g_desc[2][256];   // lookback descriptors (196 used)
__device__ unsigned           g_cnt[16];
// g_cnt: [0]=E [1]=NT1 [2]=NT2 [3]=T1 [4]=T3 [5]=INNER [6]=U [8]=T [9]=N+E

// ---------------------------------------------------------------------------
// init: occ bitset + clear bucket counters + clear presence + clear descriptors
// blocks [0,nbA): init role; blocks [nbA,..): presence-clear role
// ---------------------------------------------------------------------------
__global__ void k_init(const float* __restrict__ sdf, const float* __restrict__ th,
                       int N, int nbA) {
    if (blockIdx.x < (unsigned)nbA) {
        int gt = blockIdx.x * blockDim.x + threadIdx.x;
        int lane = threadIdx.x & 31;
        int warp = gt >> 5;
        float t = *th;
        int base = warp * 128;
#pragma unroll
        for (int it = 0; it < 4; it++) {
            int v = base + it * 32 + lane;
            unsigned o = 0;
            if (v < N) { float s = sdf[v]; o = (s > 0.0f && s <= t) ? 1u : 0u; }
            unsigned bal = __ballot_sync(FULL, o);
            if (lane == 0 && base + it * 32 < N) g_obits[warp * 4 + it] = bal;
        }
        int i4 = gt * 4;
#pragma unroll
        for (int j = 0; j < 4; j++) {
            int i = i4 + j;
            if (i < N) { g_bcnt[i] = 0u; g_bfill[i] = 0u; }
        }
        if (blockIdx.x == 0) {
            g_desc[0][threadIdx.x] = 0ull;
            g_desc[1][threadIdx.x] = 0ull;
        }
    } else {
        const unsigned NW = (MAXVAL + 15) / 16;
        unsigned i = (blockIdx.x - nbA) * blockDim.x + threadIdx.x;
        if (i < NW) g_pres4[i] = make_uint4(0u, 0u, 0u, 0u);
    }
}

// ---------------------------------------------------------------------------
// classify + bucket histogram + fused 5-channel flag block-reduce
// ---------------------------------------------------------------------------
__global__ void k_ti(const int4* __restrict__ tet, int F) {
    __shared__ unsigned long long sh64[8];
    int t = threadIdx.x, lane = t & 31, wid = t >> 5;
    int blk = blockIdx.x;
    unsigned long long p = 0;
#pragma unroll
    for (int i = 0; i < 8; i++) {
        int f = blk * 2048 + i * TPB + t;
        if (f >= F) break;
        int4 q = tet[f];
        int v[4] = {q.x, q.y, q.z, q.w};
        unsigned ti = ((g_obits[v[0] >> 5] >> (v[0] & 31)) & 1u)
                    | (((g_obits[v[1] >> 5] >> (v[1] & 31)) & 1u) << 1)
                    | (((g_obits[v[2] >> 5] >> (v[2] & 31)) & 1u) << 2)
                    | (((g_obits[v[3] >> 5] >> (v[3] & 31)) & 1u) << 3);
        g_ti[f] = (unsigned char)ti;
        p += packflags(ti);
        if (f_valid(ti)) {
#pragma unroll
            for (int e = 0; e < 6; e++) {
                int p0 = d_be[2 * e], p1 = d_be[2 * e + 1];
                if (((ti >> p0) ^ (ti >> p1)) & 1u) {
                    int a = v[p0], b = v[p1];
                    int amin = a < b ? a : b;
                    atomicAdd(&g_bcnt[amin], 1u);
                }
            }
        }
    }
#pragma unroll
    for (int d = 16; d > 0; d >>= 1)
        p += __shfl_xor_sync(FULL, p, d);
    if (lane == 0) sh64[wid] = p;
    __syncthreads();
    if (t == 0) {
        unsigned long long s = 0;
#pragma unroll
        for (int i = 0; i < 8; i++) s += sh64[i];
        g_partf[0 * 1024 + blk] = (unsigned)(s & 0xFFF);
        g_partf[1 * 1024 + blk] = (unsigned)((s >> 12) & 0xFFF);
        g_partf[2 * 1024 + blk] = (unsigned)((s >> 24) & 0xFFF);
        g_partf[3 * 1024 + blk] = (unsigned)((s >> 36) & 0xFFF);
        g_partf[4 * 1024 + blk] = (unsigned)((s >> 48) & 0xFFF);
    }
}

// 5-channel partial scan: one block per channel (parallel)
__global__ void fs_k2(int nb) {
    __shared__ unsigned shw[32];
    int c = blockIdx.x;
    int t = threadIdx.x, lane = t & 31, wid = t >> 5;
    unsigned* arr = g_partf + c * 1024;
    int base = t * 4;
    unsigned v[4]; unsigned s = 0;
#pragma unroll
    for (int i = 0; i < 4; i++) {
        unsigned x = (base + i < nb) ? arr[base + i] : 0u;
        v[i] = s; s += x;
    }
    unsigned inc = warp_iscan_u32(s, lane);
    if (lane == 31) shw[wid] = inc;
    __syncthreads();
    if (wid == 0) shw[lane] = warp_iscan_u32(shw[lane], lane);
    __syncthreads();
    unsigned wb = (wid > 0) ? shw[wid - 1] : 0u;
    unsigned excl = wb + inc - s;
#pragma unroll
    for (int i = 0; i < 4; i++)
        if (base + i < nb) arr[base + i] = excl + v[i];
    if (t == 0) g_cnt[1 + c] = shw[31];
}

// ---------------------------------------------------------------------------
// Single-pass decoupled-lookback scan over N-sized arrays.
// SAFETY: nb = ceil(N/2048) = 196 blocks => all resident in one wave on 148
// SMs, so the lookback spin cannot deadlock.
// ---------------------------------------------------------------------------
__device__ __forceinline__ unsigned* selarr(int s) {
    switch (s) {
        case 0: return g_bcnt;
        case 1: return g_boff;
        case 2: return g_ucnt;
        default: return g_urank;
    }
}

__global__ void k_scan(int insel, int outsel, int n, int counterIdx, int N, int sel) {
    __shared__ unsigned sh[8];
    __shared__ unsigned s_excl;
    const unsigned* in = selarr(insel);
    unsigned* out = selarr(outsel);
    int t = threadIdx.x, lane = t & 31, wid = t >> 5;
    int bid = blockIdx.x;
    int base = bid * (TPB * 8) + t * 8;
    unsigned v[8]; unsigned s = 0;
#pragma unroll
    for (int i = 0; i < 8; i++) {
        unsigned x = (base + i < n) ? in[base + i] : 0u;
        v[i] = s; s += x;
    }
    unsigned inc = warp_iscan_u32(s, lane);
    if (lane == 31) sh[wid] = inc;
    __syncthreads();
    if (wid == 0) {
        unsigned x = (lane < 8) ? sh[lane] : 0u;
        x = warp_iscan_u32(x, lane);
        if (lane < 8) sh[lane] = x;
    }
    __syncthreads();
    unsigned blockSum = sh[7];
    unsigned off = ((wid > 0) ? sh[wid - 1] : 0u) + inc - s;
    if (t == 0) {
        unsigned long long* desc = g_desc[sel];
        if (bid == 0) {
            __threadfence();
            atomicExch(&desc[0], (2ull << 62) | (unsigned long long)blockSum);
            s_excl = 0u;
        } else {
            __threadfence();
            atomicExch(&desc[bid], (1ull << 62) | (unsigned long long)blockSum);
            unsigned excl = 0u;
            int j = bid - 1;
            while (j >= 0) {
                unsigned long long d;
                do { d = atomicOr(&desc[j], 0ull); } while ((d >> 62) == 0ull);
                excl += (unsigned)(d & 0x3FFFFFFFFFFFFFFFull);
                if ((d >> 62) == 2ull) break;
                j--;
            }
            __threadfence();
            atomicExch(&desc[bid], (2ull << 62) | (unsigned long long)(excl + blockSum));
            s_excl = excl;
        }
    }
    __syncthreads();
    unsigned gexcl = s_excl;
#pragma unroll
    for (int i = 0; i < 8; i++)
        if (base + i < n) out[base + i] = gexcl + off + v[i];
    if (counterIdx >= 0 && bid == (int)gridDim.x - 1 && t == 0) {
        unsigned total = gexcl + blockSum;
        g_cnt[counterIdx] = total;
        if (counterIdx == 0) {
            g_cnt[8] = g_cnt[3] + 3u * g_cnt[4] + g_cnt[5];
            g_cnt[9] = (unsigned)N + total;
        }
    }
}

// ---------------------------------------------------------------------------
// scatter crossing edges into buckets
// ---------------------------------------------------------------------------
__global__ void k_scatter(const int4* __restrict__ tet, int F) {
    int f = blockIdx.x * blockDim.x + threadIdx.x;
    if (f >= F) return;
    unsigned ti = g_ti[f];
    if (!f_valid(ti)) return;
    int4 q = tet[f];
    int v[4] = {q.x, q.y, q.z, q.w};
#pragma unroll
    for (int e = 0; e < 6; e++) {
        int p0 = d_be[2 * e], p1 = d_be[2 * e + 1];
        if (((ti >> p0) ^ (ti >> p1)) & 1u) {
            int a = v[p0], b = v[p1];
            int amin = a < b ? a : b;
            int bmax = a < b ? b : a;
            unsigned p = g_boff[amin] + atomicAdd(&g_bfill[amin], 1u);
            unsigned slot = (unsigned)(6 * f + e);
            g_keys[p] = ((unsigned long long)(unsigned)bmax << 24) | (unsigned long long)slot;
        }
    }
}

// ---------------------------------------------------------------------------
// warp-cooperative shared-staging sort: one warp = 32 adjacent buckets
// ---------------------------------------------------------------------------
__global__ void __launch_bounds__(STPB) k_sort(int N) {
    __shared__ unsigned long long sbuf[STPB / 32][SPAN];
    int t = threadIdx.x, lane = t & 31, w = t >> 5;
    int a0 = (blockIdx.x * (STPB / 32) + w) * 32;
    if (a0 >= N) return;
    int last = min(a0 + 31, N - 1);
    unsigned spanStart = g_boff[a0];
    unsigned spanEnd = g_boff[last] + g_bcnt[last];
    unsigned spanLen = spanEnd - spanStart;
    int a = a0 + lane;
    unsigned off = 0, L = 0;
    if (a < N) { off = g_boff[a]; L = g_bcnt[a]; }
    unsigned u = 0;
    if (spanLen <= SPAN) {
        unsigned long long* sb = sbuf[w];
        for (unsigned i = lane; i < spanLen; i += 32)
            sb[i] = g_keys[spanStart + i];
        __syncwarp();
        if (a < N && L > 0) {
            unsigned so = off - spanStart;
            for (unsigned i = 1; i < L; i++) {
                unsigned long long key = sb[so + i];
                int j = (int)i - 1;
                while (j >= 0 && sb[so + j] > key) { sb[so + j + 1] = sb[so + j]; j--; }
                sb[so + j + 1] = key;
            }
            unsigned prevb = 0xFFFFFFFFu;
            for (unsigned i = 0; i < L; i++) {
                unsigned long long k = sb[so + i];
                unsigned b = KEY_B(k);
                unsigned head = (b != prevb) ? 1u : 0u;
                if (head) { u++; prevb = b; }
                sb[so + i] = k | ((unsigned long long)(((u - 1) << 1) | head) << 44);
            }
        }
        __syncwarp();
        for (unsigned i = lane; i < spanLen; i += 32)
            g_keys[spanStart + i] = sb[i];
    } else {
        if (a < N && L > 0) {
            for (unsigned i = 1; i < L; i++) {
                unsigned long long key = g_keys[off + i];
                int j = (int)i - 1;
                while (j >= 0 && g_keys[off + j] > key) {
                    g_keys[off + j + 1] = g_keys[off + j];
                    j--;
                }
                g_keys[off + j + 1] = key;
            }
            unsigned prevb = 0xFFFFFFFFu;
            for (unsigned i = 0; i < L; i++) {
                unsigned long long k = g_keys[off + i];
                unsigned b = KEY_B(k);
                unsigned head = (b != prevb) ? 1u : 0u;
                if (head) { u++; prevb = b; }
                g_keys[off + i] = k | ((unsigned long long)(((u - 1) << 1) | head) << 44);
            }
        }
    }
    if (a < N) g_ucnt[a] = u;
}

// ---------------------------------------------------------------------------
// fused finalize + interpolation: idxmap writes + out section 0
// ---------------------------------------------------------------------------
__global__ void k_efi(const float* __restrict__ pos, const float* __restrict__ sdf,
                      const float* __restrict__ thp, float* __restrict__ out, int N) {
    int a = blockIdx.x * blockDim.x + threadIdx.x;
    if (a >= N) return;
    unsigned off = g_boff[a];
    unsigned L = g_bcnt[a];
    if (L == 0) return;
    unsigned rb = g_urank[a];
    float th = *thp;
    float sa = sdf[a];
    float pax = pos[3 * a], pay = pos[3 * a + 1], paz = pos[3 * a + 2];
    for (unsigned i = 0; i < L; i++) {
        unsigned long long k = g_keys[off + i];
        unsigned aux = KEY_AUX(k);
        unsigned rank = rb + (aux >> 1);
        g_idxmap[KEY_SLOT(k)] = (int)rank;
        if (aux & 1u) {
            int b = (int)KEY_B(k);
            float s0 = sa, s1 = sdf[b];
            if (s0 > 0.0f && s1 > 0.0f) { s0 -= th; s1 -= th; }
            float denom = s0 - s1;
            float w0 = -s1 / denom;
            float w1 = s0 / denom;
            out[3 * (size_t)rank + 0] = pax * w0 + pos[3 * b + 0] * w1;
            out[3 * (size_t)rank + 1] = pay * w0 + pos[3 * b + 1] * w1;
            out[3 * (size_t)rank + 2] = paz * w0 + pos[3 * b + 2] * w1;
        }
    }
}

// ---------------------------------------------------------------------------
// fused emit: local flag re-scan + faces + all_tets build + presence mark
// ---------------------------------------------------------------------------
__global__ void k_emit(const int4* __restrict__ tet, int F, int N, float* __restrict__ out) {
    __shared__ unsigned long long sh64[8];
    int t = threadIdx.x, lane = t & 31, wid = t >> 5;
    int blk = blockIdx.x;
    int base = blk * (TPB * 8) + t * 8;
    unsigned lti[8];
    unsigned long long p = 0;
#pragma unroll
    for (int i = 0; i < 8; i++) {
        int f = base + i;
        lti[i] = (f < F) ? (unsigned)g_ti[f] : 0u;
        p += packflags(lti[i]);
    }
    unsigned long long inc = warp_iscan_u64(p, lane);
    if (lane == 31) sh64[wid] = inc;
    __syncthreads();
    if (t == 0) {
        unsigned long long runw = 0;
#pragma unroll
        for (int i = 0; i < 8; i++) { unsigned long long x = sh64[i]; sh64[i] = runw; runw += x; }
    }
    __syncthreads();
    unsigned long long run = sh64[wid] + inc - p;
    unsigned b0 = g_partf[0 * 1024 + blk], b1 = g_partf[1 * 1024 + blk];
    unsigned b2 = g_partf[2 * 1024 + blk], b3 = g_partf[3 * 1024 + blk];
    unsigned b4 = g_partf[4 * 1024 + blk];
    unsigned E = g_cnt[0], NT1 = g_cnt[1], T1 = g_cnt[3], T3 = g_cnt[4];
    float* fo = out + 3 * (size_t)E;
    unsigned char* pres = (unsigned char*)g_pres4;
#pragma unroll
    for (int i = 0; i < 8; i++) {
        int f = base + i;
        if (f >= F) break;
        unsigned ti = lti[i];
        if (f_valid(ti)) {
            unsigned trioff = f_nt1(ti)  ? b0 + (unsigned)(run & 0xFFF)
                                         : b1 + (unsigned)((run >> 12) & 0xFFF);
            unsigned tetoff = f_ntt1(ti) ? b2 + (unsigned)((run >> 24) & 0xFFF)
                                         : b3 + (unsigned)((run >> 36) & 0xFFF);
            int4 q = tet[f];
            int v[4] = {q.x, q.y, q.z, q.w};
            if (f_nt1(ti)) {
                size_t fb = 3 * (size_t)trioff;
#pragma unroll
                for (int j = 0; j < 3; j++)
                    fo[fb + j] = (float)g_idxmap[6 * f + d_tri[ti][j]];
            } else {
                size_t fb = 3 * (size_t)NT1 + 6 * (size_t)trioff;
#pragma unroll
                for (int j = 0; j < 6; j++)
                    fo[fb + j] = (float)g_idxmap[6 * f + d_tri[ti][j]];
            }
            if (f_ntt1(ti)) {
                int r[4];
#pragma unroll
                for (int j = 0; j < 4; j++) {
                    int c = d_tet[ti][j];
                    r[j] = (c < 4) ? v[c] : N + g_idxmap[6 * f + (c - 4)];
                    pres[r[j]] = 1;
                }
                g_alltets[tetoff] = make_int4(r[0], r[1], r[2], r[3]);
            } else {
                unsigned rowbase = T1 + 3u * tetoff;
#pragma unroll
                for (int t3i = 0; t3i < 3; t3i++) {
                    int r[4];
#pragma unroll
                    for (int j = 0; j < 4; j++) {
                        int c = d_tet[ti][4 * t3i + j];
                        r[j] = (c < 4) ? v[c] : N + g_idxmap[6 * f + (c - 4)];
                        pres[r[j]] = 1;
                    }
                    g_alltets[rowbase + t3i] = make_int4(r[0], r[1], r[2], r[3]);
                }
            }
        } else if (ti == 15u) {
            unsigned tetoff = b4 + (unsigned)((run >> 48) & 0xFFF);
            int4 q = tet[f];
            pres[q.x] = 1; pres[q.y] = 1; pres[q.z] = 1; pres[q.w] = 1;
            g_alltets[T1 + 3u * T3 + tetoff] = q;
        }
        run += packflags(ti);
    }
}

// ---------------------------------------------------------------------------
// tetmesh unique: presence byte scan over [0, N+E)
// ---------------------------------------------------------------------------
__global__ void ps_k1() {
    __shared__ unsigned sh[8];
    unsigned n = g_cnt[9];
    int t = threadIdx.x, lane = t & 31, wid = t >> 5;
    unsigned blockByteBase = blockIdx.x * (TPB * 16u);
    if (blockByteBase >= n) {
        if (t == 0) g_part2[blockIdx.x] = 0u;
        return;
    }
    const unsigned* w = (const unsigned*)g_pres4;
    const unsigned NW = (MAXVAL + 3) / 4;
    unsigned base = blockIdx.x * (TPB * 4u) + t * 4u;
    unsigned s = 0;
#pragma unroll
    for (int i = 0; i < 4; i++) {
        unsigned idx = base + i;
        if (idx < NW) s += (w[idx] * 0x01010101u) >> 24;
    }
#pragma unroll
    for (int d = 16; d > 0; d >>= 1) s += __shfl_xor_sync(FULL, s, d);
    if (lane == 0) sh[wid] = s;
    __syncthreads();
    if (t == 0) {
        unsigned tot = 0;
#pragma unroll
        for (int i = 0; i < 8; i++) tot += sh[i];
        g_part2[blockIdx.x] = tot;
    }
}

__global__ void ps_k2(int nb) {
    __shared__ unsigned shw[32];
    int t = threadIdx.x, lane = t & 31, wid = t >> 5;
    int base = t * 4;
    unsigned v[4]; unsigned s = 0;
#pragma unroll
    for (int i = 0; i < 4; i++) {
        unsigned x = (base + i < nb) ? g_part2[base + i] : 0u;
        v[i] = s; s += x;
    }
    unsigned inc = warp_iscan_u32(s, lane);
    if (lane == 31) shw[wid] = inc;
    __syncthreads();
    if (wid == 0) shw[lane] = warp_iscan_u32(shw[lane], lane);
    __syncthreads();
    unsigned wb = (wid > 0) ? shw[wid - 1] : 0u;
    unsigned excl = wb + inc - s;
#pragma unroll
    for (int i = 0; i < 4; i++)
        if (base + i < nb) g_part2[base + i] = excl + v[i];
    if (t == 0) g_cnt[6] = shw[31];
}

__global__ void ps_k3() {
    __shared__ unsigned sh[8];
    unsigned n = g_cnt[9];
    int t = threadIdx.x, lane = t & 31, wid = t >> 5;
    unsigned blockByteBase = blockIdx.x * (TPB * 16u);
    if (blockByteBase >= n) return;
    const unsigned* w = (const unsigned*)g_pres4;
    const unsigned NW = (MAXVAL + 3) / 4;
    unsigned base = blockIdx.x * (TPB * 4u) + t * 4u;
    unsigned wv[4]; unsigned s = 0;
#pragma unroll
    for (int i = 0; i < 4; i++) {
        unsigned idx = base + i;
        wv[i] = (idx < NW) ? w[idx] : 0u;
        s += (wv[i] * 0x01010101u) >> 24;
    }
    unsigned inc = warp_iscan_u32(s, lane);
    if (lane == 31) sh[wid] = inc;
    __syncthreads();
    if (t == 0) {
        unsigned runw = 0;
#pragma unroll
        for (int i = 0; i < 8; i++) { unsigned x = sh[i]; sh[i] = runw; runw += x; }
    }
    __syncthreads();
    unsigned run = g_part2[blockIdx.x] + sh[wid] + inc - s;
#pragma unroll
    for (int i = 0; i < 4; i++) {
        unsigned v = wv[i];
        unsigned byteBase = (base + i) * 4u;
#pragma unroll
        for (int bt = 0; bt < 4; bt++) {
            if ((v >> (8 * bt)) & 1u) {
                g_rank2[byteBase + bt] = run;
                run++;
            }
        }
    }
}

// ---------------------------------------------------------------------------
// fused final outputs: blocks [0,nbVt) = tetmesh verts; rest = tet indices
// ---------------------------------------------------------------------------
__global__ void k_final(const float* __restrict__ pos, int N, float* __restrict__ out,
                        int nbVt) {
    unsigned E = g_cnt[0];
    unsigned Nf = g_cnt[1] + 2u * g_cnt[2];
    if ((int)blockIdx.x < nbVt) {
        unsigned n = g_cnt[9];
        unsigned base = blockIdx.x * (TPB * 4u) + threadIdx.x;
        if (base >= n) return;
        const unsigned char* pres = (const unsigned char*)g_pres4;
        size_t ofs = (size_t)3 * E + (size_t)3 * Nf;
#pragma unroll
        for (int k4 = 0; k4 < 4; k4++) {
            unsigned v = base + k4 * TPB;
            if (v >= n) break;
            if (!pres[v]) continue;
            unsigned r = g_rank2[v];
#pragma unroll
            for (int k = 0; k < 3; k++)
                out[ofs + 3 * (size_t)r + k] =
                    (v < (unsigned)N) ? pos[3 * v + k] : out[3 * (size_t)(v - N) + k];
        }
    } else {
        unsigned bid = blockIdx.x - nbVt;
        unsigned T = g_cnt[8];
        unsigned base = bid * (TPB * 4u) + threadIdx.x;
        if (base >= T) return;
        unsigned U = g_cnt[6];
        size_t ofs = (size_t)3 * E + (size_t)3 * Nf + (size_t)3 * U;
#pragma unroll
        for (int k4 = 0; k4 < 4; k4++) {
            unsigned i = base + k4 * TPB;
            if (i >= T) break;
            int4 q = g_alltets[i];
            out[ofs + 4 * (size_t)i + 0] = (float)g_rank2[q.x];
            out[ofs + 4 * (size_t)i + 1] = (float)g_rank2[q.y];
            out[ofs + 4 * (size_t)i + 2] = (float)g_rank2[q.z];
            out[ofs + 4 * (size_t)i + 3] = (float)g_rank2[q.w];
        }
    }
}

// ---------------------------------------------------------------------------
// kernel_launch
// ---------------------------------------------------------------------------
extern "C" void kernel_launch(void* const* d_in, const int* in_sizes, int n_in,
                              void* d_out, int out_size) {
    const float* pos = (const float*)d_in[0];
    const float* sdf = (const float*)d_in[1];
    const int4*  tet = (const int4*)d_in[2];
    const float* th  = (const float*)d_in[3];
    float* out = (float*)d_out;

    int N = in_sizes[1];
    int F = in_sizes[2] / 4;

    int warpsN = (N + 127) / 128;
    int nbA = GRID(warpsN * 32);
    int nbClear = GRID((MAXVAL + 15) / 16);
    k_init<<<nbA + nbClear, TPB>>>(sdf, th, N, nbA);

    int nbf = (F + TPB * 8 - 1) / (TPB * 8);
    k_ti<<<nbf, TPB>>>(tet, F);          // classify + histogram + flag partials
    fs_k2<<<5, 1024>>>(nbf);

    int nbN = (N + TPB * 8 - 1) / (TPB * 8);   // 196 blocks: single-wave safe
    k_scan<<<nbN, TPB>>>(0, 1, N, -1, N, 0);   // bcnt -> boff
    k_scatter<<<GRID(F), TPB>>>(tet, F);
    k_sort<<<(N + STPB - 1) / STPB, STPB>>>(N);
    k_scan<<<nbN, TPB>>>(2, 3, N, 0, N, 1);    // ucnt -> urank; sets E, T, N+E

    k_efi<<<GRID(N), TPB>>>(pos, sdf, th, out, N);   // idxmap + interp verts
    k_emit<<<nbf, TPB>>>(tet, F, N, out);            // faces + all_tets + mark

    int nbp = ((MAXVAL + 3) / 4 + TPB * 4 - 1) / (TPB * 4);
    ps_k1<<<nbp, TPB>>>();
    ps_k2<<<1, 1024>>>(nbp);
    ps_k3<<<nbp, TPB>>>();

    int nbVt = GRID(MAXVAL / 4 + 1);
    k_final<<<nbVt + GRID(MAXT / 4), TPB>>>(pos, N, out, nbVt);
}

// round 10
// speedup vs baseline: 1.0159x; 1.0159x over previous
#include <cuda_runtime.h>

#define MAXN 400000
#define MAXF 2000000
#define MAXE (4 * MAXF)             // max crossing edges (<=4 per valid tet)
#define MAXSLOTNS (6 * MAXF)        // slot namespace (6f+e) for idxmap
#define MAXVAL (MAXN + MAXE)
#define MAXT (3 * MAXF)
#define TPB 256
#define STPB 128                    // sort/efi block (4 warps)
#define SPAN 1024                   // max keys per warp span (8KB smem/warp)
#define GRID(n) (((n) + TPB - 1) / TPB)
#define FULL 0xffffffffu

// key layout: [0:24) slot | [24:44) b | [44:53) aux = (localRank<<1)|head
#define KEY_SLOT(k)  ((unsigned)((k) & 0xFFFFFFull))
#define KEY_B(k)     ((unsigned)(((k) >> 24) & 0xFFFFFull))
#define KEY_AUX(k)   ((unsigned)((k) >> 44))

// ---------------------------------------------------------------------------
// Tables
// ---------------------------------------------------------------------------
__device__ const int d_tri[16][6] = {
    {-1,-1,-1,-1,-1,-1},{1,0,2,-1,-1,-1},{4,0,3,-1,-1,-1},{1,4,2,1,3,4},
    {3,1,5,-1,-1,-1},{2,3,0,2,5,3},{1,4,0,1,5,4},{4,2,5,-1,-1,-1},
    {4,5,2,-1,-1,-1},{4,1,0,4,5,1},{3,2,0,3,5,2},{1,3,5,-1,-1,-1},
    {4,1,2,4,3,1},{3,0,4,-1,-1,-1},{2,0,1,-1,-1,-1},{-1,-1,-1,-1,-1,-1}};
__device__ const int d_tet[16][12] = {
    {-1,-1,-1,-1,-1,-1,-1,-1,-1,-1,-1,-1},{0,4,5,6,-1,-1,-1,-1,-1,-1,-1,-1},
    {1,4,8,7,-1,-1,-1,-1,-1,-1,-1,-1},{7,1,8,6,5,1,7,6,5,0,1,6},
    {2,5,7,9,-1,-1,-1,-1,-1,-1,-1,-1},{4,0,6,7,9,0,7,6,7,0,9,2},
    {4,1,9,8,5,1,9,4,5,1,2,9},{6,0,1,2,8,6,1,2,9,6,8,2},
    {3,6,9,8,-1,-1,-1,-1,-1,-1,-1,-1},{5,0,4,8,5,0,8,3,5,8,9,3},
    {1,4,7,3,4,7,6,3,9,6,7,3},{0,1,5,3,5,1,9,3,5,1,7,9},
    {5,2,3,7,3,6,5,8,3,5,7,8},{0,4,7,8,0,3,8,7,0,3,7,2},
    {4,1,2,3,4,3,2,5,4,3,5,6},{0,1,2,3,-1,-1,-1,-1,-1,-1,-1,-1}};
__device__ const int d_be[12] = {0,1, 0,2, 0,3, 1,2, 1,3, 2,3};

__device__ __forceinline__ unsigned f_valid(unsigned ti) { return (0x7FFEu >> ti) & 1u; }
__device__ __forceinline__ unsigned f_nt1(unsigned ti)   { return (0x6996u >> ti) & 1u; }
__device__ __forceinline__ unsigned f_ntt1(unsigned ti)  { return (0x0116u >> ti) & 1u; }

__device__ __forceinline__ unsigned long long packflags(unsigned ti) {
    unsigned v  = f_valid(ti);
    unsigned n1 = v & f_nt1(ti);
    unsigned t1 = v & f_ntt1(ti);
    unsigned n2 = v ^ n1;
    unsigned t3 = v ^ t1;
    unsigned in = (ti == 15u) ? 1u : 0u;
    return (unsigned long long)n1
         | ((unsigned long long)n2 << 12)
         | ((unsigned long long)t1 << 24)
         | ((unsigned long long)t3 << 36)
         | ((unsigned long long)in << 48);
}

__device__ __forceinline__ unsigned warp_iscan_u32(unsigned x, int lane) {
#pragma unroll
    for (int d = 1; d < 32; d <<= 1) {
        unsigned y = __shfl_up_sync(FULL, x, d);
        if (lane >= d) x += y;
    }
    return x;
}

__device__ __forceinline__ unsigned long long warp_iscan_u64(unsigned long long x, int lane) {
#pragma unroll
    for (int d = 1; d < 32; d <<= 1) {
        unsigned long long y = __shfl_up_sync(FULL, x, d);
        if (lane >= d) x += y;
    }
    return x;
}

// ---------------------------------------------------------------------------
// Scratch
// ---------------------------------------------------------------------------
__device__ unsigned           g_obits[(MAXN + 31) / 32];
__device__ unsigned char      g_ti[MAXF];
__device__ unsigned           g_bcnt[MAXN];
__device__ unsigned           g_boff[MAXN];
__device__ unsigned           g_bfill[MAXN];
__device__ unsigned           g_ucnt[MAXN];
__device__ unsigned           g_urank[MAXN];
__device__ unsigned long long g_keys[MAXE];
__device__ int                g_idxmap[MAXSLOTNS];
__device__ int4               g_alltets[MAXT];
__device__ uint4              g_pres4[(MAXVAL + 15) / 16];
__device__ unsigned           g_rank2[MAXVAL];
__device__ unsigned           g_partf[5 * 1024];
__device__ unsigned           g_part2[4096];
__device__ unsigned long long g_desc[2][256];   // lookback descriptors (196 used)
__device__ unsigned           g_cnt[16];
// g_cnt: [0]=E [1]=NT1 [2]=NT2 [3]=T1 [4]=T3 [5]=INNER [6]=U [8]=T [9]=N+E

// ---------------------------------------------------------------------------
// init: occ bitset + clear counters + clear presence + clear descriptors
// ---------------------------------------------------------------------------
__global__ void k_init(const float* __restrict__ sdf, const float* __restrict__ th,
                       int N, int nbA) {
    if (blockIdx.x < (unsigned)nbA) {
        int gt = blockIdx.x * blockDim.x + threadIdx.x;
        int lane = threadIdx.x & 31;
        int warp = gt >> 5;
        float t = *th;
        int base = warp * 128;
#pragma unroll
        for (int it = 0; it < 4; it++) {
            int v = base + it * 32 + lane;
            unsigned o = 0;
            if (v < N) { float s = sdf[v]; o = (s > 0.0f && s <= t) ? 1u : 0u; }
            unsigned bal = __ballot_sync(FULL, o);
            if (lane == 0 && base + it * 32 < N) g_obits[warp * 4 + it] = bal;
        }
        int i4 = gt * 4;
#pragma unroll
        for (int j = 0; j < 4; j++) {
            int i = i4 + j;
            if (i < N) { g_bcnt[i] = 0u; g_bfill[i] = 0u; }
        }
        if (blockIdx.x == 0) {
            g_desc[0][threadIdx.x] = 0ull;
            g_desc[1][threadIdx.x] = 0ull;
        }
    } else {
        const unsigned NW = (MAXVAL + 15) / 16;
        unsigned i = (blockIdx.x - nbA) * blockDim.x + threadIdx.x;
        if (i < NW) g_pres4[i] = make_uint4(0u, 0u, 0u, 0u);
    }
}

// ---------------------------------------------------------------------------
// classify + bucket histogram + fused 5-channel flag block-reduce
// ---------------------------------------------------------------------------
__global__ void k_ti(const int4* __restrict__ tet, int F) {
    __shared__ unsigned long long sh64[8];
    int t = threadIdx.x, lane = t & 31, wid = t >> 5;
    int blk = blockIdx.x;
    unsigned long long p = 0;
#pragma unroll
    for (int i = 0; i < 8; i++) {
        int f = blk * 2048 + i * TPB + t;
        if (f >= F) break;
        int4 q = tet[f];
        int v[4] = {q.x, q.y, q.z, q.w};
        unsigned ti = ((g_obits[v[0] >> 5] >> (v[0] & 31)) & 1u)
                    | (((g_obits[v[1] >> 5] >> (v[1] & 31)) & 1u) << 1)
                    | (((g_obits[v[2] >> 5] >> (v[2] & 31)) & 1u) << 2)
                    | (((g_obits[v[3] >> 5] >> (v[3] & 31)) & 1u) << 3);
        g_ti[f] = (unsigned char)ti;
        p += packflags(ti);
        if (f_valid(ti)) {
#pragma unroll
            for (int e = 0; e < 6; e++) {
                int p0 = d_be[2 * e], p1 = d_be[2 * e + 1];
                if (((ti >> p0) ^ (ti >> p1)) & 1u) {
                    int a = v[p0], b = v[p1];
                    int amin = a < b ? a : b;
                    atomicAdd(&g_bcnt[amin], 1u);
                }
            }
        }
    }
#pragma unroll
    for (int d = 16; d > 0; d >>= 1)
        p += __shfl_xor_sync(FULL, p, d);
    if (lane == 0) sh64[wid] = p;
    __syncthreads();
    if (t == 0) {
        unsigned long long s = 0;
#pragma unroll
        for (int i = 0; i < 8; i++) s += sh64[i];
        g_partf[0 * 1024 + blk] = (unsigned)(s & 0xFFF);
        g_partf[1 * 1024 + blk] = (unsigned)((s >> 12) & 0xFFF);
        g_partf[2 * 1024 + blk] = (unsigned)((s >> 24) & 0xFFF);
        g_partf[3 * 1024 + blk] = (unsigned)((s >> 36) & 0xFFF);
        g_partf[4 * 1024 + blk] = (unsigned)((s >> 48) & 0xFFF);
    }
}

// 5-channel partial scan: one block per channel
__global__ void fs_k2(int nb) {
    __shared__ unsigned shw[32];
    int c = blockIdx.x;
    int t = threadIdx.x, lane = t & 31, wid = t >> 5;
    unsigned* arr = g_partf + c * 1024;
    int base = t * 4;
    unsigned v[4]; unsigned s = 0;
#pragma unroll
    for (int i = 0; i < 4; i++) {
        unsigned x = (base + i < nb) ? arr[base + i] : 0u;
        v[i] = s; s += x;
    }
    unsigned inc = warp_iscan_u32(s, lane);
    if (lane == 31) shw[wid] = inc;
    __syncthreads();
    if (wid == 0) shw[lane] = warp_iscan_u32(shw[lane], lane);
    __syncthreads();
    unsigned wb = (wid > 0) ? shw[wid - 1] : 0u;
    unsigned excl = wb + inc - s;
#pragma unroll
    for (int i = 0; i < 4; i++)
        if (base + i < nb) arr[base + i] = excl + v[i];
    if (t == 0) g_cnt[1 + c] = shw[31];
}

// ---------------------------------------------------------------------------
// Single-pass scan with PARALLEL decoupled lookback (warp-wide polling).
// SAFETY: 196 blocks => single-wave resident on 148 SMs, spin cannot deadlock.
// ---------------------------------------------------------------------------
__device__ __forceinline__ unsigned* selarr(int s) {
    switch (s) {
        case 0: return g_bcnt;
        case 1: return g_boff;
        case 2: return g_ucnt;
        default: return g_urank;
    }
}

__global__ void k_scan(int insel, int outsel, int n, int counterIdx, int N, int sel) {
    __shared__ unsigned sh[8];
    __shared__ unsigned s_excl;
    const unsigned* in = selarr(insel);
    unsigned* out = selarr(outsel);
    int t = threadIdx.x, lane = t & 31, wid = t >> 5;
    int bid = blockIdx.x;
    int base = bid * (TPB * 8) + t * 8;
    unsigned v[8]; unsigned s = 0;
#pragma unroll
    for (int i = 0; i < 8; i++) {
        unsigned x = (base + i < n) ? in[base + i] : 0u;
        v[i] = s; s += x;
    }
    unsigned inc = warp_iscan_u32(s, lane);
    if (lane == 31) sh[wid] = inc;
    __syncthreads();
    if (wid == 0) {
        unsigned x = (lane < 8) ? sh[lane] : 0u;
        x = warp_iscan_u32(x, lane);
        if (lane < 8) sh[lane] = x;
    }
    __syncthreads();
    unsigned blockSum = sh[7];
    unsigned off = ((wid > 0) ? sh[wid - 1] : 0u) + inc - s;

    unsigned long long* desc = g_desc[sel];
    if (wid == 0) {
        // publish aggregate (or inclusive for block 0) first
        if (lane == 0) {
            if (bid == 0) {
                atomicExch(&desc[0], (2ull << 62) | (unsigned long long)blockSum);
                s_excl = 0u;
            } else {
                atomicExch(&desc[bid], (1ull << 62) | (unsigned long long)blockSum);
            }
        }
        __syncwarp();
        if (bid > 0) {
            unsigned excl = 0u;
            int wbase = bid - 1;
            for (;;) {
                int j = wbase - lane;
                unsigned long long d;
                if (j >= 0) {
                    do { d = atomicOr(&desc[j], 0ull); } while ((d >> 62) == 0ull);
                } else {
                    d = (2ull << 62);   // virtual prefix 0 beyond array start
                }
                unsigned isP = ((d >> 62) == 2ull) ? 1u : 0u;
                unsigned pmask = __ballot_sync(FULL, isP);
                int firstP = __ffs(pmask) - 1;      // nearest predecessor with PREFIX
                unsigned val = (j >= 0) ? (unsigned)(d & 0x3FFFFFFFFFFFFFFFull) : 0u;
                unsigned contrib = (pmask == 0u || (int)lane <= firstP) ? val : 0u;
#pragma unroll
                for (int dd = 16; dd > 0; dd >>= 1)
                    contrib += __shfl_xor_sync(FULL, contrib, dd);
                excl += contrib;
                if (pmask != 0u) break;
                wbase -= 32;
            }
            if (lane == 0) {
                atomicExch(&desc[bid], (2ull << 62) | (unsigned long long)(excl + blockSum));
                s_excl = excl;
            }
        }
    }
    __syncthreads();
    unsigned gexcl = s_excl;
#pragma unroll
    for (int i = 0; i < 8; i++)
        if (base + i < n) out[base + i] = gexcl + off + v[i];
    if (counterIdx >= 0 && bid == (int)gridDim.x - 1 && t == 0) {
        unsigned total = gexcl + blockSum;
        g_cnt[counterIdx] = total;
        if (counterIdx == 0) {
            g_cnt[8] = g_cnt[3] + 3u * g_cnt[4] + g_cnt[5];
            g_cnt[9] = (unsigned)N + total;
        }
    }
}

// ---------------------------------------------------------------------------
// scatter crossing edges into buckets
// ---------------------------------------------------------------------------
__global__ void k_scatter(const int4* __restrict__ tet, int F) {
    int f = blockIdx.x * blockDim.x + threadIdx.x;
    if (f >= F) return;
    unsigned ti = g_ti[f];
    if (!f_valid(ti)) return;
    int4 q = tet[f];
    int v[4] = {q.x, q.y, q.z, q.w};
#pragma unroll
    for (int e = 0; e < 6; e++) {
        int p0 = d_be[2 * e], p1 = d_be[2 * e + 1];
        if (((ti >> p0) ^ (ti >> p1)) & 1u) {
            int a = v[p0], b = v[p1];
            int amin = a < b ? a : b;
            int bmax = a < b ? b : a;
            unsigned p = g_boff[amin] + atomicAdd(&g_bfill[amin], 1u);
            unsigned slot = (unsigned)(6 * f + e);
            g_keys[p] = ((unsigned long long)(unsigned)bmax << 24) | (unsigned long long)slot;
        }
    }
}

// ---------------------------------------------------------------------------
// warp-cooperative shared-staging sort: one warp = 32 adjacent buckets
// ---------------------------------------------------------------------------
__global__ void __launch_bounds__(STPB) k_sort(int N) {
    __shared__ unsigned long long sbuf[STPB / 32][SPAN];
    int t = threadIdx.x, lane = t & 31, w = t >> 5;
    int a0 = (blockIdx.x * (STPB / 32) + w) * 32;
    if (a0 >= N) return;
    int last = min(a0 + 31, N - 1);
    unsigned spanStart = g_boff[a0];
    unsigned spanEnd = g_boff[last] + g_bcnt[last];
    unsigned spanLen = spanEnd - spanStart;
    int a = a0 + lane;
    unsigned off = 0, L = 0;
    if (a < N) { off = g_boff[a]; L = g_bcnt[a]; }
    unsigned u = 0;
    if (spanLen <= SPAN) {
        unsigned long long* sb = sbuf[w];
        for (unsigned i = lane; i < spanLen; i += 32)
            sb[i] = g_keys[spanStart + i];
        __syncwarp();
        if (a < N && L > 0) {
            unsigned so = off - spanStart;
            for (unsigned i = 1; i < L; i++) {
                unsigned long long key = sb[so + i];
                int j = (int)i - 1;
                while (j >= 0 && sb[so + j] > key) { sb[so + j + 1] = sb[so + j]; j--; }
                sb[so + j + 1] = key;
            }
            unsigned prevb = 0xFFFFFFFFu;
            for (unsigned i = 0; i < L; i++) {
                unsigned long long k = sb[so + i];
                unsigned b = KEY_B(k);
                unsigned head = (b != prevb) ? 1u : 0u;
                if (head) { u++; prevb = b; }
                sb[so + i] = k | ((unsigned long long)(((u - 1) << 1) | head) << 44);
            }
        }
        __syncwarp();
        for (unsigned i = lane; i < spanLen; i += 32)
            g_keys[spanStart + i] = sb[i];
    } else {
        if (a < N && L > 0) {
            for (unsigned i = 1; i < L; i++) {
                unsigned long long key = g_keys[off + i];
                int j = (int)i - 1;
                while (j >= 0 && g_keys[off + j] > key) {
                    g_keys[off + j + 1] = g_keys[off + j];
                    j--;
                }
                g_keys[off + j + 1] = key;
            }
            unsigned prevb = 0xFFFFFFFFu;
            for (unsigned i = 0; i < L; i++) {
                unsigned long long k = g_keys[off + i];
                unsigned b = KEY_B(k);
                unsigned head = (b != prevb) ? 1u : 0u;
                if (head) { u++; prevb = b; }
                g_keys[off + i] = k | ((unsigned long long)(((u - 1) << 1) | head) << 44);
            }
        }
    }
    if (a < N) g_ucnt[a] = u;
}

// ---------------------------------------------------------------------------
// warp-staged finalize + interpolation: coalesced span load into smem,
// per-lane idxmap writes + head-edge interp
// ---------------------------------------------------------------------------
__global__ void __launch_bounds__(STPB) k_efi(const float* __restrict__ pos,
                                              const float* __restrict__ sdf,
                                              const float* __restrict__ thp,
                                              float* __restrict__ out, int N) {
    __shared__ unsigned long long sbuf[STPB / 32][SPAN];
    int t = threadIdx.x, lane = t & 31, w = t >> 5;
    int a0 = (blockIdx.x * (STPB / 32) + w) * 32;
    if (a0 >= N) return;
    int last = min(a0 + 31, N - 1);
    unsigned spanStart = g_boff[a0];
    unsigned spanEnd = g_boff[last] + g_bcnt[last];
    unsigned spanLen = spanEnd - spanStart;
    int a = a0 + lane;
    unsigned off = 0, L = 0, rb = 0;
    if (a < N) { off = g_boff[a]; L = g_bcnt[a]; rb = g_urank[a]; }
    float th = *thp;
    bool staged = (spanLen <= SPAN);
    const unsigned long long* src;
    unsigned so;
    if (staged) {
        unsigned long long* sb = sbuf[w];
        for (unsigned i = lane; i < spanLen; i += 32)
            sb[i] = g_keys[spanStart + i];
        __syncwarp();
        src = sb; so = off - spanStart;
    } else {
        src = g_keys; so = off;
    }
    if (a < N && L > 0) {
        float sa = sdf[a];
        float pax = pos[3 * a], pay = pos[3 * a + 1], paz = pos[3 * a + 2];
        for (unsigned i = 0; i < L; i++) {
            unsigned long long k = src[so + i];
            unsigned aux = KEY_AUX(k);
            unsigned rank = rb + (aux >> 1);
            g_idxmap[KEY_SLOT(k)] = (int)rank;
            if (aux & 1u) {
                int b = (int)KEY_B(k);
                float s0 = sa, s1 = sdf[b];
                if (s0 > 0.0f && s1 > 0.0f) { s0 -= th; s1 -= th; }
                float denom = s0 - s1;
                float w0 = -s1 / denom;
                float w1 = s0 / denom;
                out[3 * (size_t)rank + 0] = pax * w0 + pos[3 * b + 0] * w1;
                out[3 * (size_t)rank + 1] = pay * w0 + pos[3 * b + 1] * w1;
                out[3 * (size_t)rank + 2] = paz * w0 + pos[3 * b + 2] * w1;
            }
        }
    }
}

// ---------------------------------------------------------------------------
// fused emit: local flag re-scan + faces + all_tets build + presence mark
// ---------------------------------------------------------------------------
__global__ void k_emit(const int4* __restrict__ tet, int F, int N, float* __restrict__ out) {
    __shared__ unsigned long long sh64[8];
    int t = threadIdx.x, lane = t & 31, wid = t >> 5;
    int blk = blockIdx.x;
    int base = blk * (TPB * 8) + t * 8;
    unsigned lti[8];
    unsigned long long p = 0;
#pragma unroll
    for (int i = 0; i < 8; i++) {
        int f = base + i;
        lti[i] = (f < F) ? (unsigned)g_ti[f] : 0u;
        p += packflags(lti[i]);
    }
    unsigned long long inc = warp_iscan_u64(p, lane);
    if (lane == 31) sh64[wid] = inc;
    __syncthreads();
    if (t == 0) {
        unsigned long long runw = 0;
#pragma unroll
        for (int i = 0; i < 8; i++) { unsigned long long x = sh64[i]; sh64[i] = runw; runw += x; }
    }
    __syncthreads();
    unsigned long long run = sh64[wid] + inc - p;
    unsigned b0 = g_partf[0 * 1024 + blk], b1 = g_partf[1 * 1024 + blk];
    unsigned b2 = g_partf[2 * 1024 + blk], b3 = g_partf[3 * 1024 + blk];
    unsigned b4 = g_partf[4 * 1024 + blk];
    unsigned E = g_cnt[0], NT1 = g_cnt[1], T1 = g_cnt[3], T3 = g_cnt[4];
    float* fo = out + 3 * (size_t)E;
    unsigned char* pres = (unsigned char*)g_pres4;
#pragma unroll
    for (int i = 0; i < 8; i++) {
        int f = base + i;
        if (f >= F) break;
        unsigned ti = lti[i];
        if (f_valid(ti)) {
            unsigned trioff = f_nt1(ti)  ? b0 + (unsigned)(run & 0xFFF)
                                         : b1 + (unsigned)((run >> 12) & 0xFFF);
            unsigned tetoff = f_ntt1(ti) ? b2 + (unsigned)((run >> 24) & 0xFFF)
                                         : b3 + (unsigned)((run >> 36) & 0xFFF);
            int4 q = tet[f];
            int v[4] = {q.x, q.y, q.z, q.w};
            if (f_nt1(ti)) {
                size_t fb = 3 * (size_t)trioff;
#pragma unroll
                for (int j = 0; j < 3; j++)
                    fo[fb + j] = (float)g_idxmap[6 * f + d_tri[ti][j]];
            } else {
                size_t fb = 3 * (size_t)NT1 + 6 * (size_t)trioff;
#pragma unroll
                for (int j = 0; j < 6; j++)
                    fo[fb + j] = (float)g_idxmap[6 * f + d_tri[ti][j]];
            }
            if (f_ntt1(ti)) {
                int r[4];
#pragma unroll
                for (int j = 0; j < 4; j++) {
                    int c = d_tet[ti][j];
                    r[j] = (c < 4) ? v[c] : N + g_idxmap[6 * f + (c - 4)];
                    pres[r[j]] = 1;
                }
                g_alltets[tetoff] = make_int4(r[0], r[1], r[2], r[3]);
            } else {
                unsigned rowbase = T1 + 3u * tetoff;
#pragma unroll
                for (int t3i = 0; t3i < 3; t3i++) {
                    int r[4];
#pragma unroll
                    for (int j = 0; j < 4; j++) {
                        int c = d_tet[ti][4 * t3i + j];
                        r[j] = (c < 4) ? v[c] : N + g_idxmap[6 * f + (c - 4)];
                        pres[r[j]] = 1;
                    }
                    g_alltets[rowbase + t3i] = make_int4(r[0], r[1], r[2], r[3]);
                }
            }
        } else if (ti == 15u) {
            unsigned tetoff = b4 + (unsigned)((run >> 48) & 0xFFF);
            int4 q = tet[f];
            pres[q.x] = 1; pres[q.y] = 1; pres[q.z] = 1; pres[q.w] = 1;
            g_alltets[T1 + 3u * T3 + tetoff] = q;
        }
        run += packflags(ti);
    }
}

// ---------------------------------------------------------------------------
// tetmesh unique: presence byte scan over [0, N+E)
// ---------------------------------------------------------------------------
__global__ void ps_k1() {
    __shared__ unsigned sh[8];
    unsigned n = g_cnt[9];
    int t = threadIdx.x, lane = t & 31, wid = t >> 5;
    unsigned blockByteBase = blockIdx.x * (TPB * 16u);
    if (blockByteBase >= n) {
        if (t == 0) g_part2[blockIdx.x] = 0u;
        return;
    }
    const unsigned* w = (const unsigned*)g_pres4;
    const unsigned NW = (MAXVAL + 3) / 4;
    unsigned base = blockIdx.x * (TPB * 4u) + t * 4u;
    unsigned s = 0;
#pragma unroll
    for (int i = 0; i < 4; i++) {
        unsigned idx = base + i;
        if (idx < NW) s += (w[idx] * 0x01010101u) >> 24;
    }
#pragma unroll
    for (int d = 16; d > 0; d >>= 1) s += __shfl_xor_sync(FULL, s, d);
    if (lane == 0) sh[wid] = s;
    __syncthreads();
    if (t == 0) {
        unsigned tot = 0;
#pragma unroll
        for (int i = 0; i < 8; i++) tot += sh[i];
        g_part2[blockIdx.x] = tot;
    }
}

__global__ void ps_k2(int nb) {
    __shared__ unsigned shw[32];
    int t = threadIdx.x, lane = t & 31, wid = t >> 5;
    int base = t * 4;
    unsigned v[4]; unsigned s = 0;
#pragma unroll
    for (int i = 0; i < 4; i++) {
        unsigned x = (base + i < nb) ? g_part2[base + i] : 0u;
        v[i] = s; s += x;
    }
    unsigned inc = warp_iscan_u32(s, lane);
    if (lane == 31) shw[wid] = inc;
    __syncthreads();
    if (wid == 0) shw[lane] = warp_iscan_u32(shw[lane], lane);
    __syncthreads();
    unsigned wb = (wid > 0) ? shw[wid - 1] : 0u;
    unsigned excl = wb + inc - s;
#pragma unroll
    for (int i = 0; i < 4; i++)
        if (base + i < nb) g_part2[base + i] = excl + v[i];
    if (t == 0) g_cnt[6] = shw[31];
}

__global__ void ps_k3() {
    __shared__ unsigned sh[8];
    unsigned n = g_cnt[9];
    int t = threadIdx.x, lane = t & 31, wid = t >> 5;
    unsigned blockByteBase = blockIdx.x * (TPB * 16u);
    if (blockByteBase >= n) return;
    const unsigned* w = (const unsigned*)g_pres4;
    const unsigned NW = (MAXVAL + 3) / 4;
    unsigned base = blockIdx.x * (TPB * 4u) + t * 4u;
    unsigned wv[4]; unsigned s = 0;
#pragma unroll
    for (int i = 0; i < 4; i++) {
        unsigned idx = base + i;
        wv[i] = (idx < NW) ? w[idx] : 0u;
        s += (wv[i] * 0x01010101u) >> 24;
    }
    unsigned inc = warp_iscan_u32(s, lane);
    if (lane == 31) sh[wid] = inc;
    __syncthreads();
    if (t == 0) {
        unsigned runw = 0;
#pragma unroll
        for (int i = 0; i < 8; i++) { unsigned x = sh[i]; sh[i] = runw; runw += x; }
    }
    __syncthreads();
    unsigned run = g_part2[blockIdx.x] + sh[wid] + inc - s;
#pragma unroll
    for (int i = 0; i < 4; i++) {
        unsigned v = wv[i];
        unsigned byteBase = (base + i) * 4u;
#pragma unroll
        for (int bt = 0; bt < 4; bt++) {
            if ((v >> (8 * bt)) & 1u) {
                g_rank2[byteBase + bt] = run;
                run++;
            }
        }
    }
}

// ---------------------------------------------------------------------------
// fused final outputs: blocks [0,nbVt) = tetmesh verts; rest = tet indices
// ---------------------------------------------------------------------------
__global__ void k_final(const float* __restrict__ pos, int N, float* __restrict__ out,
                        int nbVt) {
    unsigned E = g_cnt[0];
    unsigned Nf = g_cnt[1] + 2u * g_cnt[2];
    if ((int)blockIdx.x < nbVt) {
        unsigned n = g_cnt[9];
        unsigned base = blockIdx.x * (TPB * 4u) + threadIdx.x;
        if (base >= n) return;
        const unsigned char* pres = (const unsigned char*)g_pres4;
        size_t ofs = (size_t)3 * E + (size_t)3 * Nf;
#pragma unroll
        for (int k4 = 0; k4 < 4; k4++) {
            unsigned v = base + k4 * TPB;
            if (v >= n) break;
            if (!pres[v]) continue;
            unsigned r = g_rank2[v];
#pragma unroll
            for (int k = 0; k < 3; k++)
                out[ofs + 3 * (size_t)r + k] =
                    (v < (unsigned)N) ? pos[3 * v + k] : out[3 * (size_t)(v - N) + k];
        }
    } else {
        unsigned bid = blockIdx.x - nbVt;
        unsigned T = g_cnt[8];
        unsigned base = bid * (TPB * 4u) + threadIdx.x;
        if (base >= T) return;
        unsigned U = g_cnt[6];
        size_t ofs = (size_t)3 * E + (size_t)3 * Nf + (size_t)3 * U;
#pragma unroll
        for (int k4 = 0; k4 < 4; k4++) {
            unsigned i = base + k4 * TPB;
            if (i >= T) break;
            int4 q = g_alltets[i];
            out[ofs + 4 * (size_t)i + 0] = (float)g_rank2[q.x];
            out[ofs + 4 * (size_t)i + 1] = (float)g_rank2[q.y];
            out[ofs + 4 * (size_t)i + 2] = (float)g_rank2[q.z];
            out[ofs + 4 * (size_t)i + 3] = (float)g_rank2[q.w];
        }
    }
}

// ---------------------------------------------------------------------------
// kernel_launch
// ---------------------------------------------------------------------------
extern "C" void kernel_launch(void* const* d_in, const int* in_sizes, int n_in,
                              void* d_out, int out_size) {
    const float* pos = (const float*)d_in[0];
    const float* sdf = (const float*)d_in[1];
    const int4*  tet = (const int4*)d_in[2];
    const float* th  = (const float*)d_in[3];
    float* out = (float*)d_out;

    int N = in_sizes[1];
    int F = in_sizes[2] / 4;

    int warpsN = (N + 127) / 128;
    int nbA = GRID(warpsN * 32);
    int nbClear = GRID((MAXVAL + 15) / 16);
    k_init<<<nbA + nbClear, TPB>>>(sdf, th, N, nbA);

    int nbf = (F + TPB * 8 - 1) / (TPB * 8);
    k_ti<<<nbf, TPB>>>(tet, F);          // classify + histogram + flag partials
    fs_k2<<<5, 1024>>>(nbf);

    int nbN = (N + TPB * 8 - 1) / (TPB * 8);   // 196 blocks: single-wave safe
    k_scan<<<nbN, TPB>>>(0, 1, N, -1, N, 0);   // bcnt -> boff
    k_scatter<<<GRID(F), TPB>>>(tet, F);
    k_sort<<<(N + STPB - 1) / STPB, STPB>>>(N);
    k_scan<<<nbN, TPB>>>(2, 3, N, 0, N, 1);    // ucnt -> urank; sets E, T, N+E

    k_efi<<<(N + STPB - 1) / STPB, STPB>>>(pos, sdf, th, out, N);  // idxmap + interp
    k_emit<<<nbf, TPB>>>(tet, F, N, out);                          // faces+tets+mark

    int nbp = ((MAXVAL + 3) / 4 + TPB * 4 - 1) / (TPB * 4);
    ps_k1<<<nbp, TPB>>>();
    ps_k2<<<1, 1024>>>(nbp);
    ps_k3<<<nbp, TPB>>>();

    int nbVt = GRID(MAXVAL / 4 + 1);
    k_final<<<nbVt + GRID(MAXT / 4), TPB>>>(pos, N, out, nbVt);
}